// round 16
// baseline (speedup 1.0000x reference)
#include <cuda_runtime.h>
#include <cuda_bf16.h>

#define N_GRID 64
#define N1     65
#define B_PTS  262144
#define W_FEAT 256
#define CELLS  (N_GRID * N_GRID * N_GRID)   // 262144 keys (exact cell id)

// ---------------- device scratch (no allocations allowed) ----------------
// g_hist must be ZERO at kernel_launch entry. It is zero-initialized at module
// load, and the gather kernel re-zeroes it at the end of every launch.
__device__ unsigned int g_hist[CELLS];
__device__ unsigned int g_bsums[64];        // per-scan-block sums -> exclusive prefix
__device__ unsigned int g_done;             // last-block-done counter (reset each call)
__device__ unsigned int g_perm[B_PTS];      // sorted slot -> original point id
__device__ float4       g_sorted[B_PTS];    // sorted slot -> (t0,t1,t2, packed base|valid)

// Streaming stores (evict-first: keep caches for the gather table)
__device__ __forceinline__ void st_cs_f4(float4* p, float4 v) {
    asm volatile("st.global.cs.v4.f32 [%0], {%1,%2,%3,%4};"
                 :: "l"(p), "f"(v.x), "f"(v.y), "f"(v.z), "f"(v.w) : "memory");
}
__device__ __forceinline__ void st_cs_f(float* p, float v) {
    asm volatile("st.global.cs.f32 [%0], %1;" :: "l"(p), "f"(v) : "memory");
}

__device__ __forceinline__ void point_math(float x0, float x1, float x2,
                                           int& i0, int& i1, int& i2,
                                           float& t0, float& t1, float& t2,
                                           bool& valid) {
    const float scale = (float)N_GRID / 2.0f;
    const float r0 = (x0 + 1.0f) * scale;
    const float r1 = (x1 + 1.0f) * scale;
    const float r2 = (x2 + 1.0f) * scale;
    valid = (r0 >= 0.0f) && (r0 <= (float)N_GRID) &&
            (r1 >= 0.0f) && (r1 <= (float)N_GRID) &&
            (r2 >= 0.0f) && (r2 <= (float)N_GRID);
    i0 = min(max((int)floorf(r0), 0), N_GRID - 1);
    i1 = min(max((int)floorf(r1), 0), N_GRID - 1);
    i2 = min(max((int)floorf(r2), 0), N_GRID - 1);
    t0 = r0 - (float)i0;
    t1 = r1 - (float)i1;
    t2 = r2 - (float)i2;
}

// Exact cell id, row-major (z fastest) — the proven ordering.
__device__ __forceinline__ unsigned key_of(int i0, int i1, int i2) {
    return (unsigned)((i0 * N_GRID + i1) * N_GRID + i2);
}

// ---------------- pass 1: histogram ----------------
__global__ void hist_kernel(const float* __restrict__ x) {
    int p = blockIdx.x * blockDim.x + threadIdx.x;
    if (p >= B_PTS) return;
    int i0, i1, i2; float t0, t1, t2; bool valid;
    point_math(x[p*3+0], x[p*3+1], x[p*3+2], i0, i1, i2, t0, t1, t2, valid);
    atomicAdd(&g_hist[key_of(i0, i1, i2)], 1u);
}

// ---------------- pass 2: exclusive scan, sums-scan fused (last-block pattern) ----
__global__ void __launch_bounds__(1024)
scan_block_kernel() {
    __shared__ unsigned int warp_sums[32];
    __shared__ bool s_is_last;
    const int tid  = threadIdx.x;
    const int lane = tid & 31;
    const int wid  = tid >> 5;
    const int gi   = blockIdx.x * 1024 + tid;

    uint4 v = ((const uint4*)g_hist)[gi];
    const unsigned s0 = v.x;
    const unsigned s1 = s0 + v.y;
    const unsigned s2 = s1 + v.z;
    const unsigned total = s2 + v.w;

    unsigned inc = total;
    #pragma unroll
    for (int off = 1; off < 32; off <<= 1) {
        unsigned n = __shfl_up_sync(0xFFFFFFFFu, inc, off);
        if (lane >= off) inc += n;
    }
    if (lane == 31) warp_sums[wid] = inc;
    __syncthreads();
    if (wid == 0) {
        unsigned ws = warp_sums[lane];
        unsigned wi = ws;
        #pragma unroll
        for (int off = 1; off < 32; off <<= 1) {
            unsigned n = __shfl_up_sync(0xFFFFFFFFu, wi, off);
            if (lane >= off) wi += n;
        }
        warp_sums[lane] = wi - ws;                  // exclusive warp prefix
        if (lane == 31) g_bsums[blockIdx.x] = wi;   // block total
    }
    __syncthreads();
    const unsigned excl = warp_sums[wid] + (inc - total);

    ((uint4*)g_hist)[gi] = make_uint4(excl, excl + s0, excl + s1, excl + s2);

    // ---- fused: last block to finish scans the 64 block sums ----
    __threadfence();                    // make bsums + hist writes visible
    __syncthreads();
    if (tid == 0) {
        s_is_last = (atomicAdd(&g_done, 1u) == 63u);
    }
    __syncthreads();
    if (s_is_last && wid == 0) {
        unsigned a = g_bsums[lane];
        unsigned b = g_bsums[32 + lane];
        unsigned ia = a;
        #pragma unroll
        for (int off = 1; off < 32; off <<= 1) {
            unsigned n = __shfl_up_sync(0xFFFFFFFFu, ia, off);
            if (lane >= off) ia += n;
        }
        const unsigned tot_a = __shfl_sync(0xFFFFFFFFu, ia, 31);
        unsigned ib = b;
        #pragma unroll
        for (int off = 1; off < 32; off <<= 1) {
            unsigned n = __shfl_up_sync(0xFFFFFFFFu, ib, off);
            if (lane >= off) ib += n;
        }
        g_bsums[lane]      = ia - a;                // exclusive
        g_bsums[32 + lane] = tot_a + ib - b;
        if (lane == 0) g_done = 0u;                 // reset for next launch/replay
    }
}

// ---------------- pass 3: scatter (block-sum add fused in) ----------------
__global__ void scatter_kernel(const float* __restrict__ x) {
    int p = blockIdx.x * blockDim.x + threadIdx.x;
    if (p >= B_PTS) return;
    int i0, i1, i2; float t0, t1, t2; bool valid;
    point_math(x[p*3+0], x[p*3+1], x[p*3+2], i0, i1, i2, t0, t1, t2, valid);

    const unsigned key  = key_of(i0, i1, i2);
    const unsigned slot = atomicAdd(&g_hist[key], 1u) + __ldg(&g_bsums[key >> 12]);

    const int base   = (i0 * N1 + i1) * N1 + i2;    // < 2^19
    const int packed = base | (valid ? (1 << 23) : 0);

    g_perm[slot]   = (unsigned)p;
    g_sorted[slot] = make_float4(t0, t1, t2, __int_as_float(packed));
}

// ---------------- pass 4: gather (1 warp/point, cell-sorted) + hist re-zero ----
// Gather body identical to the proven 158us kernel (256-thread blocks).
__global__ void __launch_bounds__(256)
trilerp_sorted_kernel(const float* __restrict__ gval,
                      const float4* __restrict__ gfeat,
                      float* __restrict__ out_val,
                      float4* __restrict__ out_feat)
{
    // Re-zero g_hist for the next launch (invariant: zero at entry).
    // 65536 uint4 spread over the first 256 blocks; ~1MB of extra stores.
    if (blockIdx.x < 256) {
        ((uint4*)g_hist)[blockIdx.x * blockDim.x + threadIdx.x] =
            make_uint4(0u, 0u, 0u, 0u);
    }

    const int slot = (blockIdx.x * blockDim.x + threadIdx.x) >> 5;
    const int lane = threadIdx.x & 31;
    if (slot >= B_PTS) return;

    const float4 s   = __ldg(&g_sorted[slot]);      // warp-broadcast
    const unsigned p = __ldg(&g_perm[slot]);
    const int packed = __float_as_int(s.w);
    const int base   = packed & 0x7FFFFF;
    const bool valid = (packed >> 23) & 1;

    const float wx[2] = {1.0f - s.x, s.x};
    const float wy[2] = {1.0f - s.y, s.y};
    const float wz[2] = {1.0f - s.z, s.z};

    int   flat[8];
    float w[8];
#pragma unroll
    for (int c = 0; c < 8; c++) {
        const int ox = (c >> 2) & 1, oy = (c >> 1) & 1, oz = c & 1;
        flat[c] = base + (ox * N1 + oy) * N1 + oz;
        w[c]    = wx[ox] * wy[oy] * wz[oz];
    }

    float4 acc0 = make_float4(0.f, 0.f, 0.f, 0.f);
    float4 acc1 = make_float4(0.f, 0.f, 0.f, 0.f);
    float  accv = 0.f;

    if (valid) {
#pragma unroll
        for (int c = 0; c < 8; c++) {
            const float4* row = gfeat + (size_t)flat[c] * (W_FEAT / 4);
            const float4 a = __ldg(row + lane);
            const float4 b = __ldg(row + 32 + lane);
            const float  ww = w[c];
            acc0.x = fmaf(ww, a.x, acc0.x);
            acc0.y = fmaf(ww, a.y, acc0.y);
            acc0.z = fmaf(ww, a.z, acc0.z);
            acc0.w = fmaf(ww, a.w, acc0.w);
            acc1.x = fmaf(ww, b.x, acc1.x);
            acc1.y = fmaf(ww, b.y, acc1.y);
            acc1.z = fmaf(ww, b.z, acc1.z);
            acc1.w = fmaf(ww, b.w, acc1.w);
            if (lane == 0) accv = fmaf(ww, __ldg(gval + flat[c]), accv);
        }
    }

    float4* frow = out_feat + (size_t)p * (W_FEAT / 4);
    st_cs_f4(frow + lane,      acc0);
    st_cs_f4(frow + 32 + lane, acc1);
    if (lane == 0) st_cs_f(out_val + p, accv);
}

// ---------------- launch (4 kernels) ----------------
extern "C" void kernel_launch(void* const* d_in, const int* in_sizes, int n_in,
                              void* d_out, int out_size) {
    const float* x  = (const float*)d_in[0];   // (B, 3)
    const float* gv = (const float*)d_in[1];   // (65^3, 1)
    const float* gf = (const float*)d_in[2];   // (65^3, 256)

    float* out_val  = (float*)d_out;           // (B, 1)
    float* out_feat = out_val + B_PTS;         // (B, 256)

    hist_kernel<<<B_PTS / 256, 256>>>(x);                     // 1: histogram (g_hist zero at entry)
    scan_block_kernel<<<64, 1024>>>();                        // 2: scan + fused sums-scan
    scatter_kernel<<<B_PTS / 256, 256>>>(x);                  // 3: scatter (sums-add fused)
    trilerp_sorted_kernel<<<B_PTS / 8, 256>>>(                // 4: gather + hist re-zero
        gv, (const float4*)gf, out_val, (float4*)out_feat);
}

// round 17
// speedup vs baseline: 1.1174x; 1.1174x over previous
#include <cuda_runtime.h>
#include <cuda_bf16.h>

#define N_GRID 64
#define N1     65
#define B_PTS  262144
#define W_FEAT 256
#define CELLS  (N_GRID * N_GRID * N_GRID)   // 262144 keys (exact cell id)

// ---------------- device scratch (no allocations allowed) ----------------
// g_hist must be ZERO at kernel_launch entry. It is zero-initialized at module
// load, and the gather kernel re-zeroes it on every launch.
__device__ unsigned int g_hist[CELLS];
__device__ unsigned int g_bsums[64];        // per-scan-block sums -> exclusive prefix
__device__ unsigned int g_done;             // last-block-done counter (reset each call)
__device__ unsigned int g_perm[B_PTS];      // sorted slot -> original point id
__device__ float4       g_sorted[B_PTS];    // sorted slot -> (t0,t1,t2, packed base|valid)

// ---- Blackwell 256-bit memory ops ----
__device__ __forceinline__ void ldg_nc_v8(const float* p, float* r) {
    asm volatile("ld.global.nc.v8.f32 {%0,%1,%2,%3,%4,%5,%6,%7}, [%8];"
        : "=f"(r[0]), "=f"(r[1]), "=f"(r[2]), "=f"(r[3]),
          "=f"(r[4]), "=f"(r[5]), "=f"(r[6]), "=f"(r[7])
        : "l"(p));
}
__device__ __forceinline__ void st_cs_v8(float* p, const float* r) {
    asm volatile("st.global.cs.v8.f32 [%0], {%1,%2,%3,%4,%5,%6,%7,%8};"
        :: "l"(p), "f"(r[0]), "f"(r[1]), "f"(r[2]), "f"(r[3]),
           "f"(r[4]), "f"(r[5]), "f"(r[6]), "f"(r[7]) : "memory");
}
__device__ __forceinline__ void st_cs_f(float* p, float v) {
    asm volatile("st.global.cs.f32 [%0], %1;" :: "l"(p), "f"(v) : "memory");
}

__device__ __forceinline__ void point_math(float x0, float x1, float x2,
                                           int& i0, int& i1, int& i2,
                                           float& t0, float& t1, float& t2,
                                           bool& valid) {
    const float scale = (float)N_GRID / 2.0f;
    const float r0 = (x0 + 1.0f) * scale;
    const float r1 = (x1 + 1.0f) * scale;
    const float r2 = (x2 + 1.0f) * scale;
    valid = (r0 >= 0.0f) && (r0 <= (float)N_GRID) &&
            (r1 >= 0.0f) && (r1 <= (float)N_GRID) &&
            (r2 >= 0.0f) && (r2 <= (float)N_GRID);
    i0 = min(max((int)floorf(r0), 0), N_GRID - 1);
    i1 = min(max((int)floorf(r1), 0), N_GRID - 1);
    i2 = min(max((int)floorf(r2), 0), N_GRID - 1);
    t0 = r0 - (float)i0;
    t1 = r1 - (float)i1;
    t2 = r2 - (float)i2;
}

// Exact cell id, row-major (z fastest) — the proven ordering.
__device__ __forceinline__ unsigned key_of(int i0, int i1, int i2) {
    return (unsigned)((i0 * N_GRID + i1) * N_GRID + i2);
}

// ---------------- pass 1: histogram ----------------
__global__ void hist_kernel(const float* __restrict__ x) {
    int p = blockIdx.x * blockDim.x + threadIdx.x;
    if (p >= B_PTS) return;
    int i0, i1, i2; float t0, t1, t2; bool valid;
    point_math(x[p*3+0], x[p*3+1], x[p*3+2], i0, i1, i2, t0, t1, t2, valid);
    atomicAdd(&g_hist[key_of(i0, i1, i2)], 1u);
}

// ---------------- pass 2: exclusive scan, sums-scan fused (last-block) ----------
__global__ void __launch_bounds__(1024)
scan_block_kernel() {
    __shared__ unsigned int warp_sums[32];
    __shared__ bool s_is_last;
    const int tid  = threadIdx.x;
    const int lane = tid & 31;
    const int wid  = tid >> 5;
    const int gi   = blockIdx.x * 1024 + tid;

    uint4 v = ((const uint4*)g_hist)[gi];
    const unsigned s0 = v.x;
    const unsigned s1 = s0 + v.y;
    const unsigned s2 = s1 + v.z;
    const unsigned total = s2 + v.w;

    unsigned inc = total;
    #pragma unroll
    for (int off = 1; off < 32; off <<= 1) {
        unsigned n = __shfl_up_sync(0xFFFFFFFFu, inc, off);
        if (lane >= off) inc += n;
    }
    if (lane == 31) warp_sums[wid] = inc;
    __syncthreads();
    if (wid == 0) {
        unsigned ws = warp_sums[lane];
        unsigned wi = ws;
        #pragma unroll
        for (int off = 1; off < 32; off <<= 1) {
            unsigned n = __shfl_up_sync(0xFFFFFFFFu, wi, off);
            if (lane >= off) wi += n;
        }
        warp_sums[lane] = wi - ws;                  // exclusive warp prefix
        if (lane == 31) g_bsums[blockIdx.x] = wi;   // block total
    }
    __syncthreads();
    const unsigned excl = warp_sums[wid] + (inc - total);

    ((uint4*)g_hist)[gi] = make_uint4(excl, excl + s0, excl + s1, excl + s2);

    // ---- fused: last block to finish scans the 64 block sums ----
    __threadfence();
    __syncthreads();
    if (tid == 0) s_is_last = (atomicAdd(&g_done, 1u) == 63u);
    __syncthreads();
    if (s_is_last && wid == 0) {
        unsigned a = g_bsums[lane];
        unsigned b = g_bsums[32 + lane];
        unsigned ia = a;
        #pragma unroll
        for (int off = 1; off < 32; off <<= 1) {
            unsigned n = __shfl_up_sync(0xFFFFFFFFu, ia, off);
            if (lane >= off) ia += n;
        }
        const unsigned tot_a = __shfl_sync(0xFFFFFFFFu, ia, 31);
        unsigned ib = b;
        #pragma unroll
        for (int off = 1; off < 32; off <<= 1) {
            unsigned n = __shfl_up_sync(0xFFFFFFFFu, ib, off);
            if (lane >= off) ib += n;
        }
        g_bsums[lane]      = ia - a;                // exclusive
        g_bsums[32 + lane] = tot_a + ib - b;
        if (lane == 0) g_done = 0u;                 // reset for next replay
    }
}

// ---------------- pass 3: scatter (block-sum add fused in) ----------------
__global__ void scatter_kernel(const float* __restrict__ x) {
    int p = blockIdx.x * blockDim.x + threadIdx.x;
    if (p >= B_PTS) return;
    int i0, i1, i2; float t0, t1, t2; bool valid;
    point_math(x[p*3+0], x[p*3+1], x[p*3+2], i0, i1, i2, t0, t1, t2, valid);

    const unsigned key  = key_of(i0, i1, i2);
    const unsigned slot = atomicAdd(&g_hist[key], 1u) + __ldg(&g_bsums[key >> 12]);

    const int base   = (i0 * N1 + i1) * N1 + i2;    // < 2^19
    const int packed = base | (valid ? (1 << 23) : 0);

    g_perm[slot]   = (unsigned)p;
    g_sorted[slot] = make_float4(t0, t1, t2, __int_as_float(packed));
}

// ---------------- pass 4: gather (1 warp/point, 256-bit ld/st) + hist re-zero ----
__global__ void __launch_bounds__(256)
trilerp_sorted_kernel(const float* __restrict__ gval,
                      const float* __restrict__ gfeat,
                      float* __restrict__ out_val,
                      float* __restrict__ out_feat)
{
    // Re-zero g_hist for the next launch (invariant: zero at entry).
    if (blockIdx.x < 256) {
        ((uint4*)g_hist)[blockIdx.x * blockDim.x + threadIdx.x] =
            make_uint4(0u, 0u, 0u, 0u);
    }

    const int slot = (blockIdx.x * blockDim.x + threadIdx.x) >> 5;
    const int lane = threadIdx.x & 31;
    if (slot >= B_PTS) return;

    const float4 s   = __ldg(&g_sorted[slot]);      // warp-broadcast
    const unsigned p = __ldg(&g_perm[slot]);
    const int packed = __float_as_int(s.w);
    const int base   = packed & 0x7FFFFF;
    const bool valid = (packed >> 23) & 1;

    const float wx[2] = {1.0f - s.x, s.x};
    const float wy[2] = {1.0f - s.y, s.y};
    const float wz[2] = {1.0f - s.z, s.z};

    int   flat[8];
    float w[8];
#pragma unroll
    for (int c = 0; c < 8; c++) {
        const int ox = (c >> 2) & 1, oy = (c >> 1) & 1, oz = c & 1;
        flat[c] = base + (ox * N1 + oy) * N1 + oz;
        w[c]    = wx[ox] * wy[oy] * wz[oz];
    }

    // Each lane owns channels [8*lane, 8*lane+7].
    float acc[8] = {0.f, 0.f, 0.f, 0.f, 0.f, 0.f, 0.f, 0.f};
    float accv = 0.f;

    if (valid) {
#pragma unroll
        for (int c = 0; c < 8; c++) {
            float r[8];
            ldg_nc_v8(gfeat + (size_t)flat[c] * W_FEAT + lane * 8, r);
            const float ww = w[c];
            #pragma unroll
            for (int j = 0; j < 8; j++) acc[j] = fmaf(ww, r[j], acc[j]);
            if (lane == 0) accv = fmaf(ww, __ldg(gval + flat[c]), accv);
        }
    }

    st_cs_v8(out_feat + (size_t)p * W_FEAT + lane * 8, acc);
    if (lane == 0) st_cs_f(out_val + p, accv);
}

// ---------------- launch (4 kernels) ----------------
extern "C" void kernel_launch(void* const* d_in, const int* in_sizes, int n_in,
                              void* d_out, int out_size) {
    const float* x  = (const float*)d_in[0];   // (B, 3)
    const float* gv = (const float*)d_in[1];   // (65^3, 1)
    const float* gf = (const float*)d_in[2];   // (65^3, 256)

    float* out_val  = (float*)d_out;           // (B, 1)
    float* out_feat = out_val + B_PTS;         // (B, 256)

    hist_kernel<<<B_PTS / 256, 256>>>(x);                     // 1: histogram
    scan_block_kernel<<<64, 1024>>>();                        // 2: scan + fused sums-scan
    scatter_kernel<<<B_PTS / 256, 256>>>(x);                  // 3: scatter
    trilerp_sorted_kernel<<<B_PTS / 8, 256>>>(                // 4: gather (v8 ld/st)
        gv, gf, out_val, out_feat);
}